// round 15
// baseline (speedup 1.0000x reference)
#include <cuda_runtime.h>
#include <math.h>

// GlobalAttentionPooling, single pass, load-balanced, ONE kernel.
// 4736 warp-chunks of C contiguous nodes; each warp finds piece boundaries in
// its chunk via ballots on the sorted ids, runs per-piece online softmax, and
// flushes partials (m, sum, acc[256]) to collision-free scratch. Piece flushes
// count into a per-segment atomic; the LAST flusher of a segment (threadfence
// reduction pattern) merges its <=7 pieces warp-locally and writes the output
// row — overlapped with other warps' streaming. Empty segments are zero-filled
// from id gaps. All scratch/counters are reset by their unique last toucher so
// graph replays are deterministic.

#define DD   256
#define MAXB 4096
#define NWC  4736          // total warp-chunks (1184 CTAs x 4 warps, one wave)
#define G1   1184

// segment extents + flushed-node counters (zero-init; reset by merger)
__device__ int g_ss[MAXB];
__device__ int g_es[MAXB];
__device__ int g_cnt[MAXB];

// scratch partials
__device__ float g_cp_m[NWC];
__device__ float g_cp_s[NWC];
__device__ float g_cp_acc[NWC * DD];          // whole-chunk pieces
__device__ float g_sp_m[MAXB * 2];
__device__ float g_sp_s[MAXB * 2];
__device__ float g_sp_acc[MAXB * 2 * DD];     // head(0)/tail(1) partial pieces

// Read segment id at position p. stride=2 reads the low word of int64 ids.
__device__ __forceinline__ int loadSeg(const int* __restrict__ seg32, int stride, int p) {
    return __ldg(&seg32[(size_t)p * stride]);
}

__device__ __forceinline__ float dot8(const float4& a_lo, const float4& a_hi,
                                      const float4& w_lo, const float4& w_hi) {
    float g;
    g = a_lo.x * w_lo.x;
    g = fmaf(a_lo.y, w_lo.y, g);
    g = fmaf(a_lo.z, w_lo.z, g);
    g = fmaf(a_lo.w, w_lo.w, g);
    g = fmaf(a_hi.x, w_hi.x, g);
    g = fmaf(a_hi.y, w_hi.y, g);
    g = fmaf(a_hi.z, w_hi.z, g);
    g = fmaf(a_hi.w, w_hi.w, g);
    return g;
}

// L2 (L1-bypassing) loads for cross-SM scratch readback
__device__ __forceinline__ float  ldcgf(const float* p)  { return __ldcg(p); }
__device__ __forceinline__ float4 ldcgf4(const float4* p){ return __ldcg(p); }

#define ACC_UPDATE(g, vlo, vhi)                                                   \
    do {                                                                          \
        if ((g) > m) {                                                            \
            const float r_ = __expf(m - (g));                                     \
            m = (g);                                                              \
            ssum = fmaf(ssum, r_, 1.0f);                                          \
            acc_lo.x = fmaf(acc_lo.x, r_, (vlo).x); acc_lo.y = fmaf(acc_lo.y, r_, (vlo).y); \
            acc_lo.z = fmaf(acc_lo.z, r_, (vlo).z); acc_lo.w = fmaf(acc_lo.w, r_, (vlo).w); \
            acc_hi.x = fmaf(acc_hi.x, r_, (vhi).x); acc_hi.y = fmaf(acc_hi.y, r_, (vhi).y); \
            acc_hi.z = fmaf(acc_hi.z, r_, (vhi).z); acc_hi.w = fmaf(acc_hi.w, r_, (vhi).w); \
        } else {                                                                  \
            const float e_ = __expf((g) - m);                                     \
            ssum += e_;                                                           \
            acc_lo.x = fmaf(e_, (vlo).x, acc_lo.x); acc_lo.y = fmaf(e_, (vlo).y, acc_lo.y); \
            acc_lo.z = fmaf(e_, (vlo).z, acc_lo.z); acc_lo.w = fmaf(e_, (vlo).w, acc_lo.w); \
            acc_hi.x = fmaf(e_, (vhi).x, acc_hi.x); acc_hi.y = fmaf(e_, (vhi).y, acc_hi.y); \
            acc_hi.z = fmaf(e_, (vhi).z, acc_hi.z); acc_hi.w = fmaf(e_, (vhi).w, acc_hi.w); \
        }                                                                         \
    } while (0)

__global__ __launch_bounds__(128, 8) void pool_fused(
    const float* __restrict__ feat,
    const float* __restrict__ Wg,
    const int* __restrict__ seg32,
    float* __restrict__ out,
    int n, int nseg, int C)
{
    const int lane = threadIdx.x & 31;
    const int warp = threadIdx.x >> 5;
    const int w    = blockIdx.x * 4 + warp;   // global warp-chunk id

    const int a = w * C;
    if (a >= n) return;
    const int b   = min(a + C, n);
    const int len = b - a;                    // <= 96

    // dtype detection: little-endian int64 (values < 2^31), n even -> int32
    // view at odd index n-1 is a high word = 0; sorted int32 last id != 0.
    const int stride = (__ldg(&seg32[n - 1]) == 0) ? 2 : 1;

    // ---- preload chunk ids + boundary ballots; zero-fill id gaps ----
    int      myid[3];
    unsigned bm[3];
    #pragma unroll
    for (int k = 0; k < 3; ++k) {
        const int pos = k * 32 + lane;        // relative to a
        const int abs_ = a + pos;
        int idv = 0x7fffffff, prv = 0x7fffffff;
        if (pos < len) {
            idv = loadSeg(seg32, stride, abs_);
            prv = (abs_ == 0) ? -1 : loadSeg(seg32, stride, abs_ - 1);
            // empty segments between prv and idv -> zero rows (rare/never);
            // bounds clamped to [0, nseg) so corrupt ids cannot write OOB
            const int t0 = max(prv + 1, 0);
            const int t1 = min(idv, nseg);
            for (int t = t0; t < t1; ++t) {
                float4* row = (float4*)(out + (size_t)t * DD);
                const float4 z = make_float4(0.f, 0.f, 0.f, 0.f);
                for (int q = 0; q < DD / 4; ++q) row[q] = z;
            }
        }
        myid[k] = idv;
        bm[k] = __ballot_sync(0xffffffffu, (pos > 0 && pos < len) && (idv != prv));
    }
    const int prevA = (a > 0) ? loadSeg(seg32, stride, a - 1) : -1;
    const int nextB = (b < n) ? loadSeg(seg32, stride, b) : -1;

    // trailing empty segments after the very last id (clamped to [0, nseg))
    if (b == n) {
        const int last = loadSeg(seg32, stride, n - 1);
        for (int t = max(last + 1, 0) + lane; t < nseg; t += 32) {
            float4* row = (float4*)(out + (size_t)t * DD);
            const float4 z = make_float4(0.f, 0.f, 0.f, 0.f);
            for (int q = 0; q < DD / 4; ++q) row[q] = z;
        }
    }

    const float4* W4  = (const float4*)Wg;
    const float4 w_lo = W4[lane];
    const float4 w_hi = W4[lane + 32];

    int cur = a;
    while (cur < b) {
        const int rel = cur - a;

        // next boundary strictly after rel (uniform across warp)
        int pe_rel = len;
        #pragma unroll
        for (int k = 0; k < 3; ++k) {
            const int base = k * 32;
            unsigned mm = bm[k];
            const int sh = rel + 1 - base;
            if (sh > 0) mm = (sh >= 32) ? 0u : (mm & (0xffffffffu << sh));
            const int cand = mm ? (base + __ffs(mm) - 1) : len;
            pe_rel = min(pe_rel, cand);
        }
        const int pe = a + pe_rel;

        // segment id of this piece (uniform select + broadcast + safety clamp)
        const int k_    = rel >> 5;
        const int idsel = (k_ == 0) ? myid[0] : ((k_ == 1) ? myid[1] : myid[2]);
        int s = __shfl_sync(0xffffffffu, idsel, rel & 31);
        s = min(max(s, 0), MAXB - 1);          // guard scratch indexing

        // ---- online softmax over piece [cur, pe) ----
        float4 acc_lo = make_float4(0.f, 0.f, 0.f, 0.f);
        float4 acc_hi = make_float4(0.f, 0.f, 0.f, 0.f);
        float  m = -INFINITY, ssum = 0.0f;

        int i = cur;
        for (; i + 1 < pe; i += 2) {
            const float4* r0 = (const float4*)(feat + (size_t)i * DD);
            const float4* r1 = (const float4*)(feat + (size_t)(i + 1) * DD);
            const float4 v0_lo = __ldcs(&r0[lane]);
            const float4 v0_hi = __ldcs(&r0[lane + 32]);
            const float4 v1_lo = __ldcs(&r1[lane]);
            const float4 v1_hi = __ldcs(&r1[lane + 32]);

            float g0 = dot8(v0_lo, v0_hi, w_lo, w_hi);
            float g1 = dot8(v1_lo, v1_hi, w_lo, w_hi);
            #pragma unroll
            for (int off = 16; off > 0; off >>= 1) {
                g0 += __shfl_xor_sync(0xffffffffu, g0, off);
                g1 += __shfl_xor_sync(0xffffffffu, g1, off);
            }
            ACC_UPDATE(g0, v0_lo, v0_hi);
            ACC_UPDATE(g1, v1_lo, v1_hi);
        }
        if (i < pe) {
            const float4* r0 = (const float4*)(feat + (size_t)i * DD);
            const float4 v0_lo = __ldcs(&r0[lane]);
            const float4 v0_hi = __ldcs(&r0[lane + 32]);
            float g0 = dot8(v0_lo, v0_hi, w_lo, w_hi);
            #pragma unroll
            for (int off = 16; off > 0; off >>= 1)
                g0 += __shfl_xor_sync(0xffffffffu, g0, off);
            ACC_UPDATE(g0, v0_lo, v0_hi);
        }

        // ---- flush piece ----
        const bool whole  = (cur == a) && (pe == b);
        const bool starts = (cur > a) || (prevA != s);   // piece begins segment
        const bool ends   = (pe < b) || (nextB != s);    // piece ends segment

        float* dm; float* ds; float* da;
        if (whole) {
            dm = &g_cp_m[w]; ds = &g_cp_s[w]; da = &g_cp_acc[(size_t)w * DD];
        } else {
            const int idx = s * 2 + (starts ? 0 : 1);
            dm = &g_sp_m[idx]; ds = &g_sp_s[idx]; da = &g_sp_acc[(size_t)idx * DD];
        }
        if (lane == 0) {
            *dm = m; *ds = ssum;
            if (starts) g_ss[s] = cur;
            if (ends)   g_es[s] = pe;
        }
        ((float4*)da)[lane]      = acc_lo;
        ((float4*)da)[lane + 32] = acc_hi;

        // ---- publish, count, and possibly merge (threadfence reduction) ----
        __syncwarp();
        __threadfence();
        int total = 0, ssv = 0, esv = 0;
        if (lane == 0) {
            total = atomicAdd(&g_cnt[s], pe - cur) + (pe - cur);
            ssv = __ldcg(&g_ss[s]);
            esv = __ldcg(&g_es[s]);
        }
        total = __shfl_sync(0xffffffffu, total, 0);
        ssv   = __shfl_sync(0xffffffffu, ssv, 0);
        esv   = __shfl_sync(0xffffffffu, esv, 0);

        if (esv > ssv && total == esv - ssv) {
            // this warp flushed the LAST piece of segment s -> merge now
            __threadfence();
            const int w0 = ssv / C;
            const int w1 = (esv - 1) / C;
            const int np = w1 - w0 + 1;        // <= 7

            // per-lane piece scalars (lane j holds piece j)
            float mj = -INFINITY, sj = 0.0f;
            const float* paj = 0;
            if (lane < np) {
                const int wj = w0 + lane;
                const bool wh = (ssv <= wj * C) && (esv >= min(wj * C + C, n));
                if (wh) {
                    mj  = ldcgf(&g_cp_m[wj]);
                    sj  = ldcgf(&g_cp_s[wj]);
                    paj = &g_cp_acc[(size_t)wj * DD];
                } else {
                    const int idx = s * 2 + ((wj == w0) ? 0 : 1);
                    mj  = ldcgf(&g_sp_m[idx]);
                    sj  = ldcgf(&g_sp_s[idx]);
                    paj = &g_sp_acc[(size_t)idx * DD];
                }
            }
            // global max over pieces
            float M = mj;
            #pragma unroll
            for (int off = 16; off > 0; off >>= 1)
                M = fmaxf(M, __shfl_xor_sync(0xffffffffu, M, off));

            float T = 0.0f;
            float4 o_lo = make_float4(0.f, 0.f, 0.f, 0.f);
            float4 o_hi = make_float4(0.f, 0.f, 0.f, 0.f);
            for (int j = 0; j < np; ++j) {
                const float mjj = __shfl_sync(0xffffffffu, mj, j);
                const float sjj = __shfl_sync(0xffffffffu, sj, j);
                const float* pab = (const float*)__shfl_sync(
                    0xffffffffu, (unsigned long long)paj, j);
                const float sc = __expf(mjj - M);
                T = fmaf(sjj, sc, T);
                const float4 a0 = ldcgf4(&((const float4*)pab)[lane]);
                const float4 a1 = ldcgf4(&((const float4*)pab)[lane + 32]);
                o_lo.x = fmaf(a0.x, sc, o_lo.x); o_lo.y = fmaf(a0.y, sc, o_lo.y);
                o_lo.z = fmaf(a0.z, sc, o_lo.z); o_lo.w = fmaf(a0.w, sc, o_lo.w);
                o_hi.x = fmaf(a1.x, sc, o_hi.x); o_hi.y = fmaf(a1.y, sc, o_hi.y);
                o_hi.z = fmaf(a1.z, sc, o_hi.z); o_hi.w = fmaf(a1.w, sc, o_hi.w);
            }
            const float inv = 1.0f / T;
            float4* orow = (float4*)(out + (size_t)s * DD);
            o_lo.x *= inv; o_lo.y *= inv; o_lo.z *= inv; o_lo.w *= inv;
            o_hi.x *= inv; o_hi.y *= inv; o_hi.z *= inv; o_hi.w *= inv;
            orow[lane]      = o_lo;
            orow[lane + 32] = o_hi;

            // reset segment metadata for the next graph replay (we are the
            // unique last toucher of segment s)
            if (lane == 0) {
                g_cnt[s] = 0;
                g_ss[s]  = 0;
                g_es[s]  = 0;
            }
        }

        cur = pe;
    }
}

extern "C" void kernel_launch(void* const* d_in, const int* in_sizes, int n_in,
                              void* d_out, int out_size) {
    const float* feat  = (const float*)d_in[0];
    const float* Wg    = (const float*)d_in[1];
    const int*   seg32 = (const int*)d_in[3];   // int32 view; dtype detected on device

    const int n = in_sizes[0] / DD;
    int nseg = out_size / DD;
    if (nseg > MAXB) nseg = MAXB;

    const int C = (n + NWC - 1) / NWC;          // nodes per warp-chunk

    pool_fused<<<G1, 128>>>(feat, Wg, seg32, (float*)d_out, n, nseg, C);
}